// round 1
// baseline (speedup 1.0000x reference)
#include <cuda_runtime.h>
#include <cuda_bf16.h>
#include <math.h>

// Problem constants (inputs/targets: 8192 x 2048 fp32)
#define NROWS 8192
#define NCOLS 2048
#define LAMB  0.1

// Scratch: per-row squared error
__device__ float g_err[NROWS];

// ---------------------------------------------------------------------------
// Kernel 1: err[row] = sum_d (x[row,d]-t[row,d])^2
// One block per row, 256 threads, float4 loads (2 iters per thread per array).
// HBM-bound: 128 MB read.
// ---------------------------------------------------------------------------
__global__ __launch_bounds__(256) void row_sqerr_kernel(
    const float4* __restrict__ x, const float4* __restrict__ t)
{
    const int row = blockIdx.x;
    const float4* xr = x + (size_t)row * (NCOLS / 4);
    const float4* tr = t + (size_t)row * (NCOLS / 4);

    float acc = 0.0f;
    #pragma unroll
    for (int c = threadIdx.x; c < NCOLS / 4; c += 256) {
        float4 a = xr[c];
        float4 b = tr[c];
        float d0 = a.x - b.x;
        float d1 = a.y - b.y;
        float d2 = a.z - b.z;
        float d3 = a.w - b.w;
        acc += d0 * d0 + d1 * d1 + d2 * d2 + d3 * d3;
    }

    // warp reduce
    #pragma unroll
    for (int off = 16; off > 0; off >>= 1)
        acc += __shfl_down_sync(0xFFFFFFFFu, acc, off);

    __shared__ float warp_sums[8];
    int lane = threadIdx.x & 31;
    int wid  = threadIdx.x >> 5;
    if (lane == 0) warp_sums[wid] = acc;
    __syncthreads();

    if (wid == 0) {
        float v = (lane < 8) ? warp_sums[lane] : 0.0f;
        #pragma unroll
        for (int off = 4; off > 0; off >>= 1)
            v += __shfl_down_sync(0xFFFFFFFFu, v, off);
        if (lane == 0) g_err[row] = v;
    }
}

// ---------------------------------------------------------------------------
// Kernel 2: single block, 1024 threads.
//   - bitonic sort of err[8192] ascending in smem
//   - fp64 cumsum / cumsum-of-squares via per-thread local sums + block scan
//   - evaluate h(k) for k=1..N-1, argmin with first-index tiebreak
//   - out = sum_in[k*]/k* + LAMB * h(k*)
// ---------------------------------------------------------------------------
__global__ __launch_bounds__(1024) void finalize_kernel(float* __restrict__ out)
{
    __shared__ float  s_es[NROWS];    // 32768 B
    __shared__ double s_c1[1024];     //  8192 B
    __shared__ double s_c2[1024];     //  8192 B  (total 49152 B = 48 KB)

    const int tid = threadIdx.x;
    const int N = NROWS;

    // load
    #pragma unroll
    for (int i = tid; i < N; i += 1024) s_es[i] = g_err[i];
    __syncthreads();

    // bitonic sort ascending
    for (int k = 2; k <= N; k <<= 1) {
        for (int j = k >> 1; j > 0; j >>= 1) {
            #pragma unroll
            for (int i = tid; i < N; i += 1024) {
                int ixj = i ^ j;
                if (ixj > i) {
                    bool up = ((i & k) == 0);
                    float a = s_es[i];
                    float b = s_es[ixj];
                    if ((a > b) == up) { s_es[i] = b; s_es[ixj] = a; }
                }
            }
            __syncthreads();
        }
    }

    // each thread owns 8 consecutive sorted elements
    float ev[8];
    double l1 = 0.0, l2 = 0.0;
    #pragma unroll
    for (int i = 0; i < 8; i++) {
        ev[i] = s_es[tid * 8 + i];
        double d = (double)ev[i];
        l1 += d;
        l2 += d * d;
    }
    s_c1[tid] = l1;
    s_c2[tid] = l2;
    __syncthreads();

    // inclusive Hillis-Steele scan over the 1024 per-thread partials (fp64)
    for (int off = 1; off < 1024; off <<= 1) {
        double a1 = s_c1[tid], a2 = s_c2[tid];
        double b1 = 0.0, b2 = 0.0;
        if (tid >= off) { b1 = s_c1[tid - off]; b2 = s_c2[tid - off]; }
        __syncthreads();
        s_c1[tid] = a1 + b1;
        s_c2[tid] = a2 + b2;
        __syncthreads();
    }

    double tot1 = s_c1[1023];
    double tot2 = s_c2[1023];
    double ex1  = s_c1[tid] - l1;   // exclusive prefix for this thread's chunk
    double ex2  = s_c2[tid] - l2;
    __syncthreads();  // done reading scans; arrays reused below

    const double total_scatter = tot2 - tot1 * tot1 / (double)N;

    // evaluate h(k) for this thread's 8 candidate split points
    double bestH = INFINITY;
    int    bestK = 0x7FFFFFFF;
    double bestObj = 0.0;
    double p1 = ex1, p2 = ex2;
    #pragma unroll
    for (int i = 0; i < 8; i++) {
        double d = (double)ev[i];
        p1 += d;
        p2 += d * d;
        int k = tid * 8 + i + 1;
        if (k <= N - 1) {
            double cin  = (double)k;
            double cout = (double)(N - k);
            double r1   = tot1 - p1;
            double win  = (p2 - p1 * p1 / cin) + ((tot2 - p2) - r1 * r1 / cout);
            double h    = win / total_scatter;
            if (h < bestH) {            // ascending k within thread -> first min
                bestH = h; bestK = k; bestObj = p1 / cin;
            }
        }
    }

    // block argmin reduction: s_c1 holds h; s_c2 holds packed (k, obj-bits)
    s_c1[tid] = bestH;
    long long pk = ((long long)bestK << 32) |
                   (long long)(unsigned int)__float_as_uint((float)bestObj);
    s_c2[tid] = __longlong_as_double(pk);
    __syncthreads();

    for (int s = 512; s > 0; s >>= 1) {
        if (tid < s) {
            double hA = s_c1[tid];
            double hB = s_c1[tid + s];
            long long pA = __double_as_longlong(s_c1 == s_c1 ? s_c2[tid] : s_c2[tid]); // keep simple
            long long pB = __double_as_longlong(s_c2[tid + s]);
            pA = __double_as_longlong(s_c2[tid]);
            int kA = (int)(pA >> 32);
            int kB = (int)(pB >> 32);
            if (hB < hA || (hB == hA && kB < kA)) {
                s_c1[tid] = hB;
                s_c2[tid] = s_c2[tid + s];
            }
        }
        __syncthreads();
    }

    if (tid == 0) {
        double h = s_c1[0];
        long long p = __double_as_longlong(s_c2[0]);
        float obj = __uint_as_float((unsigned int)(p & 0xFFFFFFFFll));
        out[0] = (float)((double)obj + LAMB * h);
    }
}

// ---------------------------------------------------------------------------
extern "C" void kernel_launch(void* const* d_in, const int* in_sizes, int n_in,
                              void* d_out, int out_size)
{
    const float4* x = (const float4*)d_in[0];
    const float4* t = (const float4*)d_in[1];
    float* out = (float*)d_out;

    row_sqerr_kernel<<<NROWS, 256>>>(x, t);
    finalize_kernel<<<1, 1024>>>(out);
}

// round 2
// speedup vs baseline: 1.6929x; 1.6929x over previous
#include <cuda_runtime.h>
#include <cuda_bf16.h>
#include <math.h>

// Problem constants (inputs/targets: 8192 x 2048 fp32)
#define NROWS 8192
#define NCOLS 2048
#define LAMB  0.1

// Scratch: per-row squared error (sorted in place by the bitonic kernels)
__device__ float g_err[NROWS];

// ---------------------------------------------------------------------------
// Kernel 1: err[row] = sum_d (x[row,d]-t[row,d])^2
// One block per row, 256 threads, float4 loads. HBM-bound: 128 MB read.
// ---------------------------------------------------------------------------
__global__ __launch_bounds__(256) void row_sqerr_kernel(
    const float4* __restrict__ x, const float4* __restrict__ t)
{
    const int row = blockIdx.x;
    const float4* xr = x + (size_t)row * (NCOLS / 4);
    const float4* tr = t + (size_t)row * (NCOLS / 4);

    float acc = 0.0f;
    #pragma unroll
    for (int c = threadIdx.x; c < NCOLS / 4; c += 256) {
        float4 a = xr[c];
        float4 b = tr[c];
        float d0 = a.x - b.x;
        float d1 = a.y - b.y;
        float d2 = a.z - b.z;
        float d3 = a.w - b.w;
        acc += d0 * d0 + d1 * d1 + d2 * d2 + d3 * d3;
    }

    #pragma unroll
    for (int off = 16; off > 0; off >>= 1)
        acc += __shfl_down_sync(0xFFFFFFFFu, acc, off);

    __shared__ float warp_sums[8];
    int lane = threadIdx.x & 31;
    int wid  = threadIdx.x >> 5;
    if (lane == 0) warp_sums[wid] = acc;
    __syncthreads();

    if (wid == 0) {
        float v = (lane < 8) ? warp_sums[lane] : 0.0f;
        #pragma unroll
        for (int off = 4; off > 0; off >>= 1)
            v += __shfl_down_sync(0xFFFFFFFFu, v, off);
        if (lane == 0) g_err[row] = v;
    }
}

// ---------------------------------------------------------------------------
// Bitonic sort, distributed over SMs.
// Stage (k, j): pairs (i, i+j) with (i & j)==0; ascending iff (i & k)==0.
// ---------------------------------------------------------------------------

// Phase 1: 8 blocks x 512 threads; each block sorts a 1024-element chunk in
// smem through all stages k=2..1024 (direction from GLOBAL index).
__global__ __launch_bounds__(512) void bitonic_local_sort()
{
    __shared__ float s[1024];
    const int base = blockIdx.x * 1024;
    const int t = threadIdx.x;

    s[t]       = g_err[base + t];
    s[t + 512] = g_err[base + t + 512];
    __syncthreads();

    for (int k = 2; k <= 1024; k <<= 1) {
        for (int j = k >> 1; j > 0; j >>= 1) {
            int i   = ((t & ~(j - 1)) << 1) | (t & (j - 1));
            int gi  = base + i;
            bool up = ((gi & k) == 0);
            float a = s[i];
            float b = s[i + j];
            if (up ? (a > b) : (a < b)) { s[i] = b; s[i + j] = a; }
            __syncthreads();
        }
    }

    g_err[base + t]       = s[t];
    g_err[base + t + 512] = s[t + 512];
}

// Windowed merge: 4 blocks x 1024 threads; a 2048-element smem window runs all
// sub-stages j=1024..1 of stage k (k >= 2048, so direction is constant/window).
__global__ __launch_bounds__(1024) void bitonic_local_merge(int k)
{
    __shared__ float s[2048];
    const int base = blockIdx.x * 2048;
    const int t = threadIdx.x;

    s[t]        = g_err[base + t];
    s[t + 1024] = g_err[base + t + 1024];
    __syncthreads();

    const bool up = ((base & k) == 0);
    for (int j = 1024; j > 0; j >>= 1) {
        int i = ((t & ~(j - 1)) << 1) | (t & (j - 1));
        float a = s[i];
        float b = s[i + j];
        if (up ? (a > b) : (a < b)) { s[i] = b; s[i + j] = a; }
        __syncthreads();
    }

    g_err[base + t]        = s[t];
    g_err[base + t + 1024] = s[t + 1024];
}

// Global compare-exchange for j >= 2048: 4096 independent pairs.
__global__ __launch_bounds__(256) void bitonic_global_step(int k, int j)
{
    int t = blockIdx.x * 256 + threadIdx.x;          // [0, 4096)
    int i = ((t & ~(j - 1)) << 1) | (t & (j - 1));
    bool up = ((i & k) == 0);
    float a = g_err[i];
    float b = g_err[i + j];
    if (up ? (a > b) : (a < b)) { g_err[i] = b; g_err[i + j] = a; }
}

// ---------------------------------------------------------------------------
// Finalize: g_err is sorted ascending. fp64 two-level shfl scan of
// (sum, sumsq), evaluate h(k), argmin with first-index tiebreak, write result.
// ---------------------------------------------------------------------------
__global__ __launch_bounds__(1024) void finalize_kernel(float* __restrict__ out)
{
    __shared__ double s_w1[32], s_w2[32];
    __shared__ double s_bh[32], s_bo[32];
    __shared__ int    s_bk[32];

    const int tid  = threadIdx.x;
    const int lane = tid & 31;
    const int wid  = tid >> 5;
    const int N = NROWS;

    // each thread owns 8 consecutive sorted elements
    float ev[8];
    double l1 = 0.0, l2 = 0.0;
    #pragma unroll
    for (int i = 0; i < 8; i++) {
        ev[i] = g_err[tid * 8 + i];
        double d = (double)ev[i];
        l1 += d;
        l2 += d * d;
    }

    // warp-level inclusive scan of per-thread (l1, l2)
    double i1 = l1, i2 = l2;
    #pragma unroll
    for (int off = 1; off < 32; off <<= 1) {
        double a = __shfl_up_sync(0xFFFFFFFFu, i1, off);
        double b = __shfl_up_sync(0xFFFFFFFFu, i2, off);
        if (lane >= off) { i1 += a; i2 += b; }
    }
    if (lane == 31) { s_w1[wid] = i1; s_w2[wid] = i2; }
    __syncthreads();

    // warp 0 scans the 32 warp totals
    if (wid == 0) {
        double a1 = s_w1[lane], a2 = s_w2[lane];
        #pragma unroll
        for (int off = 1; off < 32; off <<= 1) {
            double x = __shfl_up_sync(0xFFFFFFFFu, a1, off);
            double y = __shfl_up_sync(0xFFFFFFFFu, a2, off);
            if (lane >= off) { a1 += x; a2 += y; }
        }
        s_w1[lane] = a1;
        s_w2[lane] = a2;
    }
    __syncthreads();

    double base1 = (wid == 0) ? 0.0 : s_w1[wid - 1];
    double base2 = (wid == 0) ? 0.0 : s_w2[wid - 1];
    double tot1 = s_w1[31];
    double tot2 = s_w2[31];
    double ex1 = base1 + i1 - l1;   // exclusive prefix before this thread's chunk
    double ex2 = base2 + i2 - l2;

    const double total_scatter = tot2 - tot1 * tot1 / (double)N;

    // evaluate h(k) for this thread's 8 split candidates
    double bestH = INFINITY, bestObj = 0.0;
    int bestK = 0x7FFFFFFF;
    double p1 = ex1, p2 = ex2;
    #pragma unroll
    for (int i = 0; i < 8; i++) {
        double d = (double)ev[i];
        p1 += d;
        p2 += d * d;
        int k = tid * 8 + i + 1;
        if (k <= N - 1) {
            double cin  = (double)k;
            double cout = (double)(N - k);
            double r1   = tot1 - p1;
            double win  = (p2 - p1 * p1 / cin) + ((tot2 - p2) - r1 * r1 / cout);
            double h    = win / total_scatter;
            if (h < bestH) { bestH = h; bestK = k; bestObj = p1 / cin; }
        }
    }

    // warp argmin (h, then k for first-index tiebreak)
    #pragma unroll
    for (int off = 16; off > 0; off >>= 1) {
        double h2 = __shfl_down_sync(0xFFFFFFFFu, bestH, off);
        int    k2 = __shfl_down_sync(0xFFFFFFFFu, bestK, off);
        double o2 = __shfl_down_sync(0xFFFFFFFFu, bestObj, off);
        if (h2 < bestH || (h2 == bestH && k2 < bestK)) {
            bestH = h2; bestK = k2; bestObj = o2;
        }
    }
    if (lane == 0) { s_bh[wid] = bestH; s_bk[wid] = bestK; s_bo[wid] = bestObj; }
    __syncthreads();

    if (wid == 0) {
        double h = s_bh[lane];
        int    k = s_bk[lane];
        double o = s_bo[lane];
        #pragma unroll
        for (int off = 16; off > 0; off >>= 1) {
            double h2 = __shfl_down_sync(0xFFFFFFFFu, h, off);
            int    k2 = __shfl_down_sync(0xFFFFFFFFu, k, off);
            double o2 = __shfl_down_sync(0xFFFFFFFFu, o, off);
            if (h2 < h || (h2 == h && k2 < k)) { h = h2; k = k2; o = o2; }
        }
        if (lane == 0) out[0] = (float)(o + LAMB * h);
    }
}

// ---------------------------------------------------------------------------
extern "C" void kernel_launch(void* const* d_in, const int* in_sizes, int n_in,
                              void* d_out, int out_size)
{
    const float4* x = (const float4*)d_in[0];
    const float4* t = (const float4*)d_in[1];
    float* out = (float*)d_out;

    row_sqerr_kernel<<<NROWS, 256>>>(x, t);

    bitonic_local_sort<<<8, 512>>>();            // stages k = 2 .. 1024
    bitonic_local_merge<<<4, 1024>>>(2048);      // k = 2048, j = 1024..1
    bitonic_global_step<<<16, 256>>>(4096, 2048);
    bitonic_local_merge<<<4, 1024>>>(4096);      // k = 4096, j = 1024..1
    bitonic_global_step<<<16, 256>>>(8192, 4096);
    bitonic_global_step<<<16, 256>>>(8192, 2048);
    bitonic_local_merge<<<4, 1024>>>(8192);      // k = 8192, j = 1024..1

    finalize_kernel<<<1, 1024>>>(out);
}